// round 10
// baseline (speedup 1.0000x reference)
#include <cuda_runtime.h>
#include <cuda_fp16.h>
#include <math.h>
#include <cstdint>

// Problem constants (fixed by the reference)
#define NMAX   100000
#define EMAX   1600000
#define HID    256
#define INC    512
#define NLAYER 8
#define ALPHA  0.1f

// ---------------- device scratch (no allocation allowed) ----------------
__device__ int    g_deg[NMAX];
__device__ float  g_dinv[NMAX];
__device__ int    g_rowptr[NMAX + 1];
__device__ int    g_cursor[NMAX];
__device__ int    g_srcs[EMAX];
__device__ float  g_wts[EMAX];
__device__ int    g_bsums[256];
__device__ __align__(128) __half g_x16[(size_t)NMAX * INC];    // fp16 copy of x
__device__ __align__(128) __half g_h016[(size_t)NMAX * HID];   // fp16 embed output (residual + l0 gather)
__device__ __align__(128) __half g_h16[(size_t)NMAX * HID];    // fp16 rotating gather array (GEMM out)
__device__ __align__(128) __half g_p16[(size_t)NMAX * HID];    // fp16 SpMM output (GEMM in)
__device__ __align__(128) __half g_W16E[(size_t)HID * INC];            // embed weight, [N,K] fp16
__device__ __align__(128) __half g_W16L[(size_t)NLAYER * HID * HID];   // folded layer weights (1-b)I+bW, [N,K] fp16

// ---------------- small helpers ----------------
__device__ __forceinline__ uint32_t smem_u32(const void* p) {
    uint32_t a;
    asm("{ .reg .u64 t; cvta.to.shared.u64 t, %1; cvt.u32.u64 %0, t; }" : "=r"(a) : "l"(p));
    return a;
}
__device__ __forceinline__ void cp_async16(uint32_t dst, const void* src) {
    asm volatile("cp.async.cg.shared.global [%0], [%1], 16;" :: "r"(dst), "l"(src));
}
#define CP_COMMIT() asm volatile("cp.async.commit_group;" ::: "memory")
#define CP_WAIT(n)  asm volatile("cp.async.wait_group %0;" :: "n"(n) : "memory")

__device__ __forceinline__ void ldsm_x4(uint32_t& r0, uint32_t& r1, uint32_t& r2,
                                        uint32_t& r3, uint32_t addr) {
    asm volatile("ldmatrix.sync.aligned.m8n8.x4.shared.b16 {%0,%1,%2,%3}, [%4];"
                 : "=r"(r0), "=r"(r1), "=r"(r2), "=r"(r3) : "r"(addr));
}

// ---------------- graph preprocessing ----------------
__global__ void k_deg_init(int n) {
    int i = blockIdx.x * blockDim.x + threadIdx.x;
    if (i < n) g_deg[i] = 1;  // self loop
}

__global__ void k_deg_count(const int* __restrict__ ei, int E) {
    int e = blockIdx.x * blockDim.x + threadIdx.x;
    if (e < E) atomicAdd(&g_deg[ei[E + e]], 1);   // col = target
}

__global__ void k_dinv(int n) {
    int i = blockIdx.x * blockDim.x + threadIdx.x;
    if (i < n) g_dinv[i] = rsqrtf((float)g_deg[i]);
}

__global__ void k_scan_blocks(int n) {
    __shared__ int s[1024];
    int t = threadIdx.x;
    int i = blockIdx.x * 1024 + t;
    int v = (i < n) ? (g_deg[i] - 1) : 0;
    s[t] = v;
    __syncthreads();
    for (int off = 1; off < 1024; off <<= 1) {
        int x = (t >= off) ? s[t - off] : 0;
        __syncthreads();
        s[t] += x;
        __syncthreads();
    }
    if (i < n) g_rowptr[i + 1] = s[t];
    if (t == 1023) g_bsums[blockIdx.x] = s[1023];
}

__global__ void k_scan_sums(int nb) {
    __shared__ int s[128];
    int t = threadIdx.x;
    int v = (t < nb) ? g_bsums[t] : 0;
    s[t] = v;
    __syncthreads();
    for (int off = 1; off < 128; off <<= 1) {
        int x = (t >= off) ? s[t - off] : 0;
        __syncthreads();
        s[t] += x;
        __syncthreads();
    }
    if (t < 128) g_bsums[t] = s[t] - v;  // exclusive
}

__global__ void k_finalize_ptrs(int n) {
    int i = blockIdx.x * blockDim.x + threadIdx.x;
    if (i >= n) return;
    int off = g_bsums[i >> 10];
    int incl = g_rowptr[i + 1] + off;
    g_rowptr[i + 1] = incl;
    g_cursor[i] = incl - (g_deg[i] - 1);
    if (i == 0) g_rowptr[0] = 0;
}

__global__ void k_scatter(const int* __restrict__ ei, int E) {
    int e = blockIdx.x * blockDim.x + threadIdx.x;
    if (e >= E) return;
    int src = ei[e];
    int dst = ei[E + e];
    int p = atomicAdd(&g_cursor[dst], 1);
    g_srcs[p] = src;
    g_wts[p] = g_dinv[src] * g_dinv[dst];
}

// fp32 -> fp16 bulk convert (8 elems/thread)
__global__ void k_tohalf(const float* __restrict__ in, __half* __restrict__ out, size_t n8) {
    size_t i = (size_t)blockIdx.x * blockDim.x + threadIdx.x;
    if (i >= n8) return;
    const float4* in4 = (const float4*)in;
    float4 a = in4[2 * i], b = in4[2 * i + 1];
    uint4 ov;
    __half2* o2 = (__half2*)&ov;
    o2[0] = __floats2half2_rn(a.x, a.y);
    o2[1] = __floats2half2_rn(a.z, a.w);
    o2[2] = __floats2half2_rn(b.x, b.y);
    o2[3] = __floats2half2_rn(b.z, b.w);
    ((uint4*)out)[i] = ov;
}

// Transpose to [N,K] fp16: out[n*K+k] = h(in[k*N+n])
__global__ void k_transpose_h(const float* __restrict__ in, __half* __restrict__ out,
                              int K, int N) {
    __shared__ float t[32][33];
    int k0 = blockIdx.x * 32, n0 = blockIdx.y * 32;
    for (int i = threadIdx.y; i < 32; i += 8)
        t[i][threadIdx.x] = in[(size_t)(k0 + i) * N + n0 + threadIdx.x];
    __syncthreads();
    for (int i = threadIdx.y; i < 32; i += 8)
        out[(size_t)(n0 + i) * K + k0 + threadIdx.x] = __float2half(t[threadIdx.x][i]);
}

// Folded layer weights: out[n*K+k] = h( beta*W[k][n] + (k==n)*(1-beta) ), layer = blockIdx.z
__global__ void k_transpose_fold(const float* __restrict__ in, __half* __restrict__ out,
                                 int K, int N) {
    __shared__ float t[32][33];
    int l = blockIdx.z;
    float beta = logf(0.5f / (float)(l + 1) + 1.0f);
    int k0 = blockIdx.x * 32, n0 = blockIdx.y * 32;
    const float* src = in  + (size_t)l * K * N;
    __half*      dst = out + (size_t)l * K * N;
    for (int i = threadIdx.y; i < 32; i += 8)
        t[i][threadIdx.x] = src[(size_t)(k0 + i) * N + n0 + threadIdx.x];
    __syncthreads();
    for (int i = threadIdx.y; i < 32; i += 8) {
        int k = k0 + threadIdx.x, nn = n0 + i;
        float v = beta * t[threadIdx.x][i] + ((k == nn) ? (1.0f - beta) : 0.0f);
        dst[(size_t)nn * K + k] = __float2half(v);
    }
}

// ---------------- SpMM (all-fp16 I/O, fp32 accum): one warp per node ----------------
__global__ void __launch_bounds__(256) k_spmm16(const __half* __restrict__ hin,
                                                const __half* __restrict__ res,
                                                __half* __restrict__ outp,
                                                int n) {
    int warp = (blockIdx.x * blockDim.x + threadIdx.x) >> 5;
    int lane = threadIdx.x & 31;
    if (warp >= n) return;
    int node = warp;

    const uint4* hin4 = (const uint4*)hin;   // 8 halves per uint4; 32 uint4 per row

    float di = g_dinv[node];
    float ws = di * di;

    float acc[8];
    {
        uint4 v = hin4[(size_t)node * 32 + lane];
        const __half2* h2 = (const __half2*)&v;
        #pragma unroll
        for (int q = 0; q < 4; q++) {
            float2 f = __half22float2(h2[q]);
            acc[q * 2]     = ws * f.x;
            acc[q * 2 + 1] = ws * f.y;
        }
    }

    int start = g_rowptr[node];
    int end   = g_rowptr[node + 1];
    for (int p0 = start; p0 < end; p0 += 32) {
        int myp = p0 + lane;
        int src = 0;
        float w = 0.f;
        if (myp < end) {
            src = g_srcs[myp];
            w   = g_wts[myp];
        }
        int cnt = min(32, end - p0);
        #pragma unroll 4
        for (int j = 0; j < cnt; j++) {
            int   s  = __shfl_sync(0xffffffffu, src, j);
            float wj = __shfl_sync(0xffffffffu, w, j);
            uint4 v = hin4[(size_t)s * 32 + lane];
            const __half2* h2 = (const __half2*)&v;
            #pragma unroll
            for (int q = 0; q < 4; q++) {
                float2 f = __half22float2(h2[q]);
                acc[q * 2]     += wj * f.x;
                acc[q * 2 + 1] += wj * f.y;
            }
        }
    }

    uint4 rv = ((const uint4*)res)[(size_t)node * 32 + lane];
    const __half2* r2 = (const __half2*)&rv;
    uint4 ov;
    __half2* o2 = (__half2*)&ov;
    #pragma unroll
    for (int q = 0; q < 4; q++) {
        float2 f = __half22float2(r2[q]);
        o2[q] = __floats2half2_rn((1.f - ALPHA) * acc[q * 2]     + ALPHA * f.x,
                                  (1.f - ALPHA) * acc[q * 2 + 1] + ALPHA * f.y);
    }
    ((uint4*)outp)[(size_t)node * 32 + lane] = ov;
}

// ====== FP16 mma.sync GEMM: 128x256 tile, 512 thr / 16 warps (32x64 each), ======
// ====== ldmatrix + 3-stage cp.async, A read ONCE (full-HID N tile)          ======
// A16 row-major [M,K] fp16, B16 K-major [N=256,K] fp16 (= col-major B), fp32 accum.
// smem rows = 32 halves (64B = 4 x 16B chunks); chunk swizzle c ^ ((row>>1)&3).
#define STAGE_B 24576                // bytes/stage: A 128x64B=8KB + B 256x64B=16KB
#define GEMM_SMEM (3 * STAGE_B)      // 72 KB dynamic

__global__ void __launch_bounds__(512, 1) k_hgemm(const __half* __restrict__ A16,
                                                  const __half* __restrict__ B16,
                                                  const float* __restrict__ bias,
                                                  float* __restrict__ out32,
                                                  __half* __restrict__ out16,
                                                  int M, int K, int do_relu) {
    extern __shared__ __align__(16) uint32_t smem[];

    const int tid  = threadIdx.x;
    const int warp = tid >> 5;
    const int lane = tid & 31;
    const int gid  = lane >> 2;   // 0..7
    const int tig  = lane & 3;    // 0..3
    const int wm   = warp >> 2;   // 0..3  (M offset wm*32)
    const int wn   = warp & 3;    // 0..3  (N offset wn*64)
    const int rowBase = blockIdx.x * 128;

    const int nch = K >> 5;

    float acc[2][8][4];
    #pragma unroll
    for (int i = 0; i < 2; i++)
        #pragma unroll
        for (int j = 0; j < 8; j++)
            #pragma unroll
            for (int q = 0; q < 4; q++) acc[i][j][q] = 0.f;

    const uint32_t smem_base = smem_u32(smem);

    // ---- precomputed ldmatrix lane offsets (stage-relative) ----
    uint32_t offA[2], offB[2];
    {
        int rA = (lane & 7) + ((lane >> 3) & 1) * 8;
        int cA = (lane >> 4) & 1;
        int rowA = wm * 32 + rA;
        int sA = (rowA >> 1) & 3;
        int rB = (lane & 7) + ((lane >> 4) & 1) * 8;
        int cB = (lane >> 3) & 1;
        int rowB = wn * 64 + rB;
        int sB = (rowB >> 1) & 3;
        #pragma unroll
        for (int ks = 0; ks < 2; ks++) {
            offA[ks] = (uint32_t)(rowA * 64 + (((ks * 2 + cA) ^ sA) << 4));
            offB[ks] = (uint32_t)(8192 + rowB * 64 + (((ks * 2 + cB) ^ sB) << 4));
        }
    }

    auto load_chunk = [&](int c) {
        const int k0 = c << 5;
        const uint32_t stg = smem_base + (uint32_t)((c % 3) * STAGE_B);
        {   // A: 128 rows x 4 chunks = 512 transfers (1/thread)
            int r  = tid >> 2;
            int c4 = tid & 3;
            int gr = min(rowBase + r, M - 1);
            cp_async16(stg + (uint32_t)(r * 64 + ((c4 ^ ((r >> 1) & 3)) << 4)),
                       &A16[(size_t)gr * K + k0 + c4 * 8]);
        }
        const uint32_t stgB = stg + 8192;
        #pragma unroll
        for (int p = 0; p < 2; p++) {   // B: 256 rows x 4 chunks = 1024 transfers (2/thread)
            int r  = p * 128 + (tid >> 2);
            int c4 = tid & 3;
            cp_async16(stgB + (uint32_t)(r * 64 + ((c4 ^ ((r >> 1) & 3)) << 4)),
                       &B16[(size_t)r * K + k0 + c4 * 8]);
        }
        CP_COMMIT();
    };

    load_chunk(0);
    load_chunk(1);

    for (int c = 0; c < nch; c++) {
        if (c + 1 < nch) { CP_WAIT(1); } else { CP_WAIT(0); }
        __syncthreads();                    // stage c ready; all warps past compute c-1
        if (c + 2 < nch) load_chunk(c + 2); // overwrites stage (c-1)%3 — safe after sync

        const uint32_t stg = smem_base + (uint32_t)((c % 3) * STAGE_B);

        #pragma unroll
        for (int ks = 0; ks < 2; ks++) {
            uint32_t af[2][4];
            #pragma unroll
            for (int mt = 0; mt < 2; mt++)
                ldsm_x4(af[mt][0], af[mt][1], af[mt][2], af[mt][3],
                        stg + offA[ks] + (uint32_t)(mt * 1024));
            uint32_t bf[8][2];
            #pragma unroll
            for (int p = 0; p < 4; p++)
                ldsm_x4(bf[2 * p][0], bf[2 * p][1], bf[2 * p + 1][0], bf[2 * p + 1][1],
                        stg + offB[ks] + (uint32_t)(p * 1024));
            #pragma unroll
            for (int mt = 0; mt < 2; mt++)
                #pragma unroll
                for (int nt = 0; nt < 8; nt++) {
                    asm volatile(
                        "mma.sync.aligned.m16n8k16.row.col.f32.f16.f16.f32 "
                        "{%0,%1,%2,%3}, {%4,%5,%6,%7}, {%8,%9}, {%0,%1,%2,%3};"
                        : "+f"(acc[mt][nt][0]), "+f"(acc[mt][nt][1]),
                          "+f"(acc[mt][nt][2]), "+f"(acc[mt][nt][3])
                        : "r"(af[mt][0]), "r"(af[mt][1]), "r"(af[mt][2]), "r"(af[mt][3]),
                          "r"(bf[nt][0]), "r"(bf[nt][1]));
                }
        }
    }

    // ---- epilogue ----
    #pragma unroll
    for (int mt = 0; mt < 2; mt++) {
        int rbase = rowBase + wm * 32 + mt * 16 + gid;
        #pragma unroll
        for (int nt = 0; nt < 8; nt++) {
            int cc = wn * 64 + nt * 8 + tig * 2;
            #pragma unroll
            for (int half = 0; half < 2; half++) {
                int r = rbase + half * 8;
                if (r >= M) continue;
                float v0 = acc[mt][nt][half * 2 + 0];
                float v1 = acc[mt][nt][half * 2 + 1];
                if (bias) {
                    v0 += bias[cc];
                    v1 += bias[cc + 1];
                }
                if (do_relu) {
                    v0 = fmaxf(v0, 0.f);
                    v1 = fmaxf(v1, 0.f);
                }
                size_t o = (size_t)r * HID + cc;
                if (out32) {
                    float2 vo; vo.x = v0; vo.y = v1;
                    *(float2*)&out32[o] = vo;
                }
                if (out16)
                    *(__half2*)&out16[o] = __floats2half2_rn(v0, v1);
            }
        }
    }
}

// ---------------- host orchestration ----------------
extern "C" void kernel_launch(void* const* d_in, const int* in_sizes, int n_in,
                              void* d_out, int out_size) {
    const float* x      = (const float*)d_in[0];
    const int*   ei     = (const int*)d_in[1];
    const float* Wemb   = (const float*)d_in[2];
    const float* bemb   = (const float*)d_in[3];
    const float* Wconvs = (const float*)d_in[4];
    float* out = (float*)d_out;

    int M = in_sizes[0] / INC;
    int E = in_sizes[1] / 2;

    __half *x16, *h016, *h16, *p16, *W16E, *W16L;
    cudaGetSymbolAddress((void**)&x16,  g_x16);
    cudaGetSymbolAddress((void**)&h016, g_h016);
    cudaGetSymbolAddress((void**)&h16,  g_h16);
    cudaGetSymbolAddress((void**)&p16,  g_p16);
    cudaGetSymbolAddress((void**)&W16E, g_W16E);
    cudaGetSymbolAddress((void**)&W16L, g_W16L);

    cudaFuncSetAttribute(k_hgemm, cudaFuncAttributeMaxDynamicSharedMemorySize, GEMM_SMEM);

    const int T = 256;
    int nbN = (M + T - 1) / T;
    int nbE = (E + T - 1) / T;
    int nbScan = (M + 1023) / 1024;
    int ggrid = (M + 127) / 128;

    // weights + x conversion first; embed GEMM is the 4th launch (ncu window)
    k_transpose_h<<<dim3(INC / 32, HID / 32), dim3(32, 8)>>>(Wemb, W16E, INC, HID);
    k_transpose_fold<<<dim3(HID / 32, HID / 32, NLAYER), dim3(32, 8)>>>(Wconvs, W16L, HID, HID);
    {
        size_t n8 = (size_t)M * INC / 8;
        k_tohalf<<<(unsigned)((n8 + 255) / 256), 256>>>(x, x16, n8);
    }

    // embed: h016 = h16(relu(x @ Wemb + bemb))
    k_hgemm<<<ggrid, 512, GEMM_SMEM>>>(x16, W16E, bemb, nullptr, h016, M, INC, 1);

    // graph preprocessing
    k_deg_init<<<nbN, T>>>(M);
    k_deg_count<<<nbE, T>>>(ei, E);
    k_dinv<<<nbN, T>>>(M);
    k_scan_blocks<<<nbScan, 1024>>>(M);
    k_scan_sums<<<1, 128>>>(nbScan);
    k_finalize_ptrs<<<nbN, T>>>(M);
    k_scatter<<<nbE, T>>>(ei, E);

    // layers: SpMM (fp16 in/out) then folded-weight GEMM
    int spmmBlocks = ((M * 32) + T - 1) / T;
    for (int l = 0; l < NLAYER; l++) {
        const __half* gatherIn = (l == 0) ? h016 : h16;
        k_spmm16<<<spmmBlocks, T>>>(gatherIn, h016, p16, M);
        int last = (l == NLAYER - 1);
        if (last)
            k_hgemm<<<ggrid, 512, GEMM_SMEM>>>(p16, W16L + (size_t)l * HID * HID, nullptr,
                                               out, nullptr, M, HID, 0);
        else
            k_hgemm<<<ggrid, 512, GEMM_SMEM>>>(p16, W16L + (size_t)l * HID * HID, nullptr,
                                               nullptr, h16, M, HID, 1);
    }
}

// round 11
// speedup vs baseline: 1.0958x; 1.0958x over previous
#include <cuda_runtime.h>
#include <cuda_fp16.h>
#include <math.h>
#include <cstdint>

// Problem constants (fixed by the reference)
#define NMAX   100000
#define EMAX   1600000
#define HID    256
#define INC    512
#define NLAYER 8
#define ALPHA  0.1f

// ---------------- device scratch (no allocation allowed) ----------------
__device__ int    g_deg[NMAX];
__device__ float  g_dinv[NMAX];
__device__ int    g_rowptr[NMAX + 1];
__device__ int    g_cursor[NMAX];
__device__ int    g_srcs[EMAX];
__device__ float  g_wts[EMAX];
__device__ int    g_bsums[256];
__device__ __align__(128) __half g_x16[(size_t)NMAX * INC];    // fp16 copy of x
__device__ __align__(128) __half g_h016[(size_t)NMAX * HID];   // fp16 embed output (residual + l0 gather)
__device__ __align__(128) __half g_h16[(size_t)NMAX * HID];    // fp16 rotating gather array (GEMM out)
__device__ __align__(128) __half g_p16[(size_t)NMAX * HID];    // fp16 SpMM output (GEMM in)
__device__ __align__(128) __half g_W16E[(size_t)HID * INC];            // embed weight, [N,K] fp16
__device__ __align__(128) __half g_W16L[(size_t)NLAYER * HID * HID];   // folded layer weights (1-b)I+bW, [N,K] fp16

// ---------------- small helpers ----------------
__device__ __forceinline__ uint32_t smem_u32(const void* p) {
    uint32_t a;
    asm("{ .reg .u64 t; cvta.to.shared.u64 t, %1; cvt.u32.u64 %0, t; }" : "=r"(a) : "l"(p));
    return a;
}
__device__ __forceinline__ void cp_async16(uint32_t dst, const void* src) {
    asm volatile("cp.async.cg.shared.global [%0], [%1], 16;" :: "r"(dst), "l"(src));
}
#define CP_COMMIT() asm volatile("cp.async.commit_group;" ::: "memory")
#define CP_WAIT(n)  asm volatile("cp.async.wait_group %0;" :: "n"(n) : "memory")

__device__ __forceinline__ void ldsm_x4(uint32_t& r0, uint32_t& r1, uint32_t& r2,
                                        uint32_t& r3, uint32_t addr) {
    asm volatile("ldmatrix.sync.aligned.m8n8.x4.shared.b16 {%0,%1,%2,%3}, [%4];"
                 : "=r"(r0), "=r"(r1), "=r"(r2), "=r"(r3) : "r"(addr));
}

// ---------------- graph preprocessing ----------------
__global__ void k_deg_init(int n) {
    int i = blockIdx.x * blockDim.x + threadIdx.x;
    if (i < n) g_deg[i] = 1;  // self loop
}

__global__ void k_deg_count(const int* __restrict__ ei, int E) {
    int e = blockIdx.x * blockDim.x + threadIdx.x;
    if (e < E) atomicAdd(&g_deg[ei[E + e]], 1);   // col = target
}

__global__ void k_dinv(int n) {
    int i = blockIdx.x * blockDim.x + threadIdx.x;
    if (i < n) g_dinv[i] = rsqrtf((float)g_deg[i]);
}

__global__ void k_scan_blocks(int n) {
    __shared__ int s[1024];
    int t = threadIdx.x;
    int i = blockIdx.x * 1024 + t;
    int v = (i < n) ? (g_deg[i] - 1) : 0;
    s[t] = v;
    __syncthreads();
    for (int off = 1; off < 1024; off <<= 1) {
        int x = (t >= off) ? s[t - off] : 0;
        __syncthreads();
        s[t] += x;
        __syncthreads();
    }
    if (i < n) g_rowptr[i + 1] = s[t];
    if (t == 1023) g_bsums[blockIdx.x] = s[1023];
}

__global__ void k_scan_sums(int nb) {
    __shared__ int s[128];
    int t = threadIdx.x;
    int v = (t < nb) ? g_bsums[t] : 0;
    s[t] = v;
    __syncthreads();
    for (int off = 1; off < 128; off <<= 1) {
        int x = (t >= off) ? s[t - off] : 0;
        __syncthreads();
        s[t] += x;
        __syncthreads();
    }
    if (t < 128) g_bsums[t] = s[t] - v;  // exclusive
}

__global__ void k_finalize_ptrs(int n) {
    int i = blockIdx.x * blockDim.x + threadIdx.x;
    if (i >= n) return;
    int off = g_bsums[i >> 10];
    int incl = g_rowptr[i + 1] + off;
    g_rowptr[i + 1] = incl;
    g_cursor[i] = incl - (g_deg[i] - 1);
    if (i == 0) g_rowptr[0] = 0;
}

__global__ void k_scatter(const int* __restrict__ ei, int E) {
    int e = blockIdx.x * blockDim.x + threadIdx.x;
    if (e >= E) return;
    int src = ei[e];
    int dst = ei[E + e];
    int p = atomicAdd(&g_cursor[dst], 1);
    g_srcs[p] = src;
    g_wts[p] = g_dinv[src] * g_dinv[dst];
}

// fp32 -> fp16 bulk convert (8 elems/thread)
__global__ void k_tohalf(const float* __restrict__ in, __half* __restrict__ out, size_t n8) {
    size_t i = (size_t)blockIdx.x * blockDim.x + threadIdx.x;
    if (i >= n8) return;
    const float4* in4 = (const float4*)in;
    float4 a = in4[2 * i], b = in4[2 * i + 1];
    uint4 ov;
    __half2* o2 = (__half2*)&ov;
    o2[0] = __floats2half2_rn(a.x, a.y);
    o2[1] = __floats2half2_rn(a.z, a.w);
    o2[2] = __floats2half2_rn(b.x, b.y);
    o2[3] = __floats2half2_rn(b.z, b.w);
    ((uint4*)out)[i] = ov;
}

// Transpose to [N,K] fp16: out[n*K+k] = h(in[k*N+n])
__global__ void k_transpose_h(const float* __restrict__ in, __half* __restrict__ out,
                              int K, int N) {
    __shared__ float t[32][33];
    int k0 = blockIdx.x * 32, n0 = blockIdx.y * 32;
    for (int i = threadIdx.y; i < 32; i += 8)
        t[i][threadIdx.x] = in[(size_t)(k0 + i) * N + n0 + threadIdx.x];
    __syncthreads();
    for (int i = threadIdx.y; i < 32; i += 8)
        out[(size_t)(n0 + i) * K + k0 + threadIdx.x] = __float2half(t[threadIdx.x][i]);
}

// Folded layer weights: out[n*K+k] = h( beta*W[k][n] + (k==n)*(1-beta) ), layer = blockIdx.z
__global__ void k_transpose_fold(const float* __restrict__ in, __half* __restrict__ out,
                                 int K, int N) {
    __shared__ float t[32][33];
    int l = blockIdx.z;
    float beta = logf(0.5f / (float)(l + 1) + 1.0f);
    int k0 = blockIdx.x * 32, n0 = blockIdx.y * 32;
    const float* src = in  + (size_t)l * K * N;
    __half*      dst = out + (size_t)l * K * N;
    for (int i = threadIdx.y; i < 32; i += 8)
        t[i][threadIdx.x] = src[(size_t)(k0 + i) * N + n0 + threadIdx.x];
    __syncthreads();
    for (int i = threadIdx.y; i < 32; i += 8) {
        int k = k0 + threadIdx.x, nn = n0 + i;
        float v = beta * t[threadIdx.x][i] + ((k == nn) ? (1.0f - beta) : 0.0f);
        dst[(size_t)nn * K + k] = __float2half(v);
    }
}

// ---------------- SpMM (all-fp16 I/O, fp32 accum): one warp per node ----------------
__global__ void __launch_bounds__(256) k_spmm16(const __half* __restrict__ hin,
                                                const __half* __restrict__ res,
                                                __half* __restrict__ outp,
                                                int n) {
    int warp = (blockIdx.x * blockDim.x + threadIdx.x) >> 5;
    int lane = threadIdx.x & 31;
    if (warp >= n) return;
    int node = warp;

    const uint4* hin4 = (const uint4*)hin;   // 8 halves per uint4; 32 uint4 per row

    float di = g_dinv[node];
    float ws = di * di;

    float acc[8];
    {
        uint4 v = hin4[(size_t)node * 32 + lane];
        const __half2* h2 = (const __half2*)&v;
        #pragma unroll
        for (int q = 0; q < 4; q++) {
            float2 f = __half22float2(h2[q]);
            acc[q * 2]     = ws * f.x;
            acc[q * 2 + 1] = ws * f.y;
        }
    }

    int start = g_rowptr[node];
    int end   = g_rowptr[node + 1];
    for (int p0 = start; p0 < end; p0 += 32) {
        int myp = p0 + lane;
        int src = 0;
        float w = 0.f;
        if (myp < end) {
            src = g_srcs[myp];
            w   = g_wts[myp];
        }
        int cnt = min(32, end - p0);
        #pragma unroll 4
        for (int j = 0; j < cnt; j++) {
            int   s  = __shfl_sync(0xffffffffu, src, j);
            float wj = __shfl_sync(0xffffffffu, w, j);
            uint4 v = hin4[(size_t)s * 32 + lane];
            const __half2* h2 = (const __half2*)&v;
            #pragma unroll
            for (int q = 0; q < 4; q++) {
                float2 f = __half22float2(h2[q]);
                acc[q * 2]     += wj * f.x;
                acc[q * 2 + 1] += wj * f.y;
            }
        }
    }

    uint4 rv = ((const uint4*)res)[(size_t)node * 32 + lane];
    const __half2* r2 = (const __half2*)&rv;
    uint4 ov;
    __half2* o2 = (__half2*)&ov;
    #pragma unroll
    for (int q = 0; q < 4; q++) {
        float2 f = __half22float2(r2[q]);
        o2[q] = __floats2half2_rn((1.f - ALPHA) * acc[q * 2]     + ALPHA * f.x,
                                  (1.f - ALPHA) * acc[q * 2 + 1] + ALPHA * f.y);
    }
    ((uint4*)outp)[(size_t)node * 32 + lane] = ov;
}

// ====== FP16 mma.sync GEMM: 128x128 tile, 256 thr / 8 warps (32x64 each), ======
// ====== ldmatrix + 3-stage cp.async (R9 structure, doubled warps)         ======
// A16 row-major [M,K] fp16, B16 K-major [N,K] fp16 (= col-major B), fp32 accum.
// smem rows = 32 halves (64B = 4 x 16B chunks); chunk swizzle c ^ ((row>>1)&3).
#define STAGE_B 16384                // bytes per stage: A 8KB + B 8KB

__global__ void __launch_bounds__(256, 2) k_hgemm(const __half* __restrict__ A16,
                                                  const __half* __restrict__ B16,
                                                  const float* __restrict__ bias,
                                                  float* __restrict__ out32,
                                                  __half* __restrict__ out16,
                                                  int M, int K, int do_relu) {
    __shared__ __align__(16) uint32_t smem[3 * STAGE_B / 4];  // 48 KB

    const int tid  = threadIdx.x;
    const int warp = tid >> 5;
    const int lane = tid & 31;
    const int gid  = lane >> 2;   // 0..7
    const int tig  = lane & 3;    // 0..3
    const int wm   = warp >> 1;   // 0..3  (M offset wm*32)
    const int wn   = warp & 1;    // 0..1  (N offset wn*64)
    const int rowBase = blockIdx.y * 128;
    const int colBase = blockIdx.x * 128;

    const int nch = K >> 5;

    float acc[2][8][4];
    #pragma unroll
    for (int i = 0; i < 2; i++)
        #pragma unroll
        for (int j = 0; j < 8; j++)
            #pragma unroll
            for (int q = 0; q < 4; q++) acc[i][j][q] = 0.f;

    const uint32_t smem_base = smem_u32(smem);

    // ---- precomputed ldmatrix lane offsets (stage-relative) ----
    uint32_t offA[2], offB[2];
    {
        int rA = (lane & 7) + ((lane >> 3) & 1) * 8;
        int cA = (lane >> 4) & 1;
        int rowA = wm * 32 + rA;
        int sA = (rowA >> 1) & 3;
        int rB = (lane & 7) + ((lane >> 4) & 1) * 8;
        int cB = (lane >> 3) & 1;
        int rowB = wn * 64 + rB;
        int sB = (rowB >> 1) & 3;
        #pragma unroll
        for (int ks = 0; ks < 2; ks++) {
            offA[ks] = (uint32_t)(rowA * 64 + (((ks * 2 + cA) ^ sA) << 4));
            offB[ks] = (uint32_t)(8192 + rowB * 64 + (((ks * 2 + cB) ^ sB) << 4));
        }
    }

    auto load_chunk = [&](int c) {
        const int k0 = c << 5;
        const uint32_t stg = smem_base + (uint32_t)((c % 3) * STAGE_B);
        #pragma unroll
        for (int p = 0; p < 2; p++) {   // A: 128 rows x 4 chunks, 256 threads -> 2 each
            int r  = p * 64 + (tid >> 2);
            int c4 = tid & 3;
            int gr = min(rowBase + r, M - 1);
            cp_async16(stg + (uint32_t)(r * 64 + ((c4 ^ ((r >> 1) & 3)) << 4)),
                       &A16[(size_t)gr * K + k0 + c4 * 8]);
        }
        const uint32_t stgB = stg + 8192;
        #pragma unroll
        for (int p = 0; p < 2; p++) {   // B: 128 rows x 4 chunks
            int r  = p * 64 + (tid >> 2);
            int c4 = tid & 3;
            cp_async16(stgB + (uint32_t)(r * 64 + ((c4 ^ ((r >> 1) & 3)) << 4)),
                       &B16[(size_t)(colBase + r) * K + k0 + c4 * 8]);
        }
        CP_COMMIT();
    };

    load_chunk(0);
    load_chunk(1);

    for (int c = 0; c < nch; c++) {
        if (c + 1 < nch) { CP_WAIT(1); } else { CP_WAIT(0); }
        __syncthreads();                    // stage c ready; all warps past compute c-1
        if (c + 2 < nch) load_chunk(c + 2); // overwrites stage (c-1)%3 — safe after sync

        const uint32_t stg = smem_base + (uint32_t)((c % 3) * STAGE_B);

        #pragma unroll
        for (int ks = 0; ks < 2; ks++) {
            uint32_t af[2][4];
            #pragma unroll
            for (int mt = 0; mt < 2; mt++)
                ldsm_x4(af[mt][0], af[mt][1], af[mt][2], af[mt][3],
                        stg + offA[ks] + (uint32_t)(mt * 1024));
            uint32_t bf[8][2];
            #pragma unroll
            for (int p = 0; p < 4; p++)
                ldsm_x4(bf[2 * p][0], bf[2 * p][1], bf[2 * p + 1][0], bf[2 * p + 1][1],
                        stg + offB[ks] + (uint32_t)(p * 1024));
            #pragma unroll
            for (int mt = 0; mt < 2; mt++)
                #pragma unroll
                for (int nt = 0; nt < 8; nt++) {
                    asm volatile(
                        "mma.sync.aligned.m16n8k16.row.col.f32.f16.f16.f32 "
                        "{%0,%1,%2,%3}, {%4,%5,%6,%7}, {%8,%9}, {%0,%1,%2,%3};"
                        : "+f"(acc[mt][nt][0]), "+f"(acc[mt][nt][1]),
                          "+f"(acc[mt][nt][2]), "+f"(acc[mt][nt][3])
                        : "r"(af[mt][0]), "r"(af[mt][1]), "r"(af[mt][2]), "r"(af[mt][3]),
                          "r"(bf[nt][0]), "r"(bf[nt][1]));
                }
        }
    }

    // ---- epilogue ----
    #pragma unroll
    for (int mt = 0; mt < 2; mt++) {
        int rbase = rowBase + wm * 32 + mt * 16 + gid;
        #pragma unroll
        for (int nt = 0; nt < 8; nt++) {
            int cc = colBase + wn * 64 + nt * 8 + tig * 2;
            #pragma unroll
            for (int half = 0; half < 2; half++) {
                int r = rbase + half * 8;
                if (r >= M) continue;
                float v0 = acc[mt][nt][half * 2 + 0];
                float v1 = acc[mt][nt][half * 2 + 1];
                if (bias) {
                    v0 += bias[cc];
                    v1 += bias[cc + 1];
                }
                if (do_relu) {
                    v0 = fmaxf(v0, 0.f);
                    v1 = fmaxf(v1, 0.f);
                }
                size_t o = (size_t)r * HID + cc;
                if (out32) {
                    float2 vo; vo.x = v0; vo.y = v1;
                    *(float2*)&out32[o] = vo;
                }
                if (out16)
                    *(__half2*)&out16[o] = __floats2half2_rn(v0, v1);
            }
        }
    }
}

// ---------------- host orchestration ----------------
extern "C" void kernel_launch(void* const* d_in, const int* in_sizes, int n_in,
                              void* d_out, int out_size) {
    const float* x      = (const float*)d_in[0];
    const int*   ei     = (const int*)d_in[1];
    const float* Wemb   = (const float*)d_in[2];
    const float* bemb   = (const float*)d_in[3];
    const float* Wconvs = (const float*)d_in[4];
    float* out = (float*)d_out;

    int M = in_sizes[0] / INC;
    int E = in_sizes[1] / 2;

    __half *x16, *h016, *h16, *p16, *W16E, *W16L;
    cudaGetSymbolAddress((void**)&x16,  g_x16);
    cudaGetSymbolAddress((void**)&h016, g_h016);
    cudaGetSymbolAddress((void**)&h16,  g_h16);
    cudaGetSymbolAddress((void**)&p16,  g_p16);
    cudaGetSymbolAddress((void**)&W16E, g_W16E);
    cudaGetSymbolAddress((void**)&W16L, g_W16L);

    const int T = 256;
    int nbN = (M + T - 1) / T;
    int nbE = (E + T - 1) / T;
    int nbScan = (M + 1023) / 1024;
    dim3 ggrid(HID / 128, (M + 127) / 128);

    // weights + x conversion first; embed GEMM is the 4th launch (ncu window)
    k_transpose_h<<<dim3(INC / 32, HID / 32), dim3(32, 8)>>>(Wemb, W16E, INC, HID);
    k_transpose_fold<<<dim3(HID / 32, HID / 32, NLAYER), dim3(32, 8)>>>(Wconvs, W16L, HID, HID);
    {
        size_t n8 = (size_t)M * INC / 8;
        k_tohalf<<<(unsigned)((n8 + 255) / 256), 256>>>(x, x16, n8);
    }

    // embed: h016 = h16(relu(x @ Wemb + bemb))
    k_hgemm<<<ggrid, 256>>>(x16, W16E, bemb, nullptr, h016, M, INC, 1);

    // graph preprocessing
    k_deg_init<<<nbN, T>>>(M);
    k_deg_count<<<nbE, T>>>(ei, E);
    k_dinv<<<nbN, T>>>(M);
    k_scan_blocks<<<nbScan, 1024>>>(M);
    k_scan_sums<<<1, 128>>>(nbScan);
    k_finalize_ptrs<<<nbN, T>>>(M);
    k_scatter<<<nbE, T>>>(ei, E);

    // layers: SpMM (fp16 in/out) then folded-weight GEMM
    int spmmBlocks = ((M * 32) + T - 1) / T;
    for (int l = 0; l < NLAYER; l++) {
        const __half* gatherIn = (l == 0) ? h016 : h16;
        k_spmm16<<<spmmBlocks, T>>>(gatherIn, h016, p16, M);
        int last = (l == NLAYER - 1);
        if (last)
            k_hgemm<<<ggrid, 256>>>(p16, W16L + (size_t)l * HID * HID, nullptr,
                                    out, nullptr, M, HID, 0);
        else
            k_hgemm<<<ggrid, 256>>>(p16, W16L + (size_t)l * HID * HID, nullptr,
                                    nullptr, h16, M, HID, 1);
    }
}

// round 12
// speedup vs baseline: 1.1298x; 1.0310x over previous
#include <cuda_runtime.h>
#include <cuda_fp16.h>
#include <math.h>
#include <cstdint>

// Problem constants (fixed by the reference)
#define NMAX   100000
#define EMAX   1600000
#define HID    256
#define INC    512
#define NLAYER 8
#define ALPHA  0.1f

// ---------------- device scratch (no allocation allowed) ----------------
__device__ int    g_deg[NMAX];
__device__ float  g_dinv[NMAX];
__device__ int    g_rowptr[NMAX + 1];
__device__ int    g_cursor[NMAX];
__device__ int    g_srcs[EMAX];
__device__ float  g_wts[EMAX];
__device__ int    g_bsums[256];
__device__ __align__(128) __half g_x16[(size_t)NMAX * INC];    // fp16 copy of x
__device__ __align__(128) __half g_h016[(size_t)NMAX * HID];   // fp16 embed output (residual + l0 gather)
__device__ __align__(128) __half g_h16[(size_t)NMAX * HID];    // fp16 rotating gather array (GEMM out)
__device__ __align__(128) __half g_p16[(size_t)NMAX * HID];    // fp16 SpMM output (GEMM in)
__device__ __align__(128) __half g_W16E[(size_t)HID * INC];            // embed weight, [N,K] fp16
__device__ __align__(128) __half g_W16L[(size_t)NLAYER * HID * HID];   // folded layer weights (1-b)I+bW, [N,K] fp16

// ---------------- small helpers ----------------
__device__ __forceinline__ uint32_t smem_u32(const void* p) {
    uint32_t a;
    asm("{ .reg .u64 t; cvta.to.shared.u64 t, %1; cvt.u32.u64 %0, t; }" : "=r"(a) : "l"(p));
    return a;
}
__device__ __forceinline__ void cp_async16(uint32_t dst, const void* src) {
    asm volatile("cp.async.cg.shared.global [%0], [%1], 16;" :: "r"(dst), "l"(src));
}
#define CP_COMMIT() asm volatile("cp.async.commit_group;" ::: "memory")
#define CP_WAIT(n)  asm volatile("cp.async.wait_group %0;" :: "n"(n) : "memory")

__device__ __forceinline__ void ldsm_x4(uint32_t& r0, uint32_t& r1, uint32_t& r2,
                                        uint32_t& r3, uint32_t addr) {
    asm volatile("ldmatrix.sync.aligned.m8n8.x4.shared.b16 {%0,%1,%2,%3}, [%4];"
                 : "=r"(r0), "=r"(r1), "=r"(r2), "=r"(r3) : "r"(addr));
}

// ---------------- graph preprocessing ----------------
__global__ void k_deg_init(int n) {
    int i = blockIdx.x * blockDim.x + threadIdx.x;
    if (i < n) g_deg[i] = 1;  // self loop
}

__global__ void k_deg_count(const int* __restrict__ ei, int E) {
    int e = blockIdx.x * blockDim.x + threadIdx.x;
    if (e < E) atomicAdd(&g_deg[ei[E + e]], 1);   // col = target
}

__global__ void k_dinv(int n) {
    int i = blockIdx.x * blockDim.x + threadIdx.x;
    if (i < n) g_dinv[i] = rsqrtf((float)g_deg[i]);
}

__global__ void k_scan_blocks(int n) {
    __shared__ int s[1024];
    int t = threadIdx.x;
    int i = blockIdx.x * 1024 + t;
    int v = (i < n) ? (g_deg[i] - 1) : 0;
    s[t] = v;
    __syncthreads();
    for (int off = 1; off < 1024; off <<= 1) {
        int x = (t >= off) ? s[t - off] : 0;
        __syncthreads();
        s[t] += x;
        __syncthreads();
    }
    if (i < n) g_rowptr[i + 1] = s[t];
    if (t == 1023) g_bsums[blockIdx.x] = s[1023];
}

__global__ void k_scan_sums(int nb) {
    __shared__ int s[128];
    int t = threadIdx.x;
    int v = (t < nb) ? g_bsums[t] : 0;
    s[t] = v;
    __syncthreads();
    for (int off = 1; off < 128; off <<= 1) {
        int x = (t >= off) ? s[t - off] : 0;
        __syncthreads();
        s[t] += x;
        __syncthreads();
    }
    if (t < 128) g_bsums[t] = s[t] - v;  // exclusive
}

__global__ void k_finalize_ptrs(int n) {
    int i = blockIdx.x * blockDim.x + threadIdx.x;
    if (i >= n) return;
    int off = g_bsums[i >> 10];
    int incl = g_rowptr[i + 1] + off;
    g_rowptr[i + 1] = incl;
    g_cursor[i] = incl - (g_deg[i] - 1);
    if (i == 0) g_rowptr[0] = 0;
}

__global__ void k_scatter(const int* __restrict__ ei, int E) {
    int e = blockIdx.x * blockDim.x + threadIdx.x;
    if (e >= E) return;
    int src = ei[e];
    int dst = ei[E + e];
    int p = atomicAdd(&g_cursor[dst], 1);
    g_srcs[p] = src;
    g_wts[p] = g_dinv[src] * g_dinv[dst];
}

// fp32 -> fp16 bulk convert (8 elems/thread)
__global__ void k_tohalf(const float* __restrict__ in, __half* __restrict__ out, size_t n8) {
    size_t i = (size_t)blockIdx.x * blockDim.x + threadIdx.x;
    if (i >= n8) return;
    const float4* in4 = (const float4*)in;
    float4 a = in4[2 * i], b = in4[2 * i + 1];
    uint4 ov;
    __half2* o2 = (__half2*)&ov;
    o2[0] = __floats2half2_rn(a.x, a.y);
    o2[1] = __floats2half2_rn(a.z, a.w);
    o2[2] = __floats2half2_rn(b.x, b.y);
    o2[3] = __floats2half2_rn(b.z, b.w);
    ((uint4*)out)[i] = ov;
}

// Transpose to [N,K] fp16: out[n*K+k] = h(in[k*N+n])
__global__ void k_transpose_h(const float* __restrict__ in, __half* __restrict__ out,
                              int K, int N) {
    __shared__ float t[32][33];
    int k0 = blockIdx.x * 32, n0 = blockIdx.y * 32;
    for (int i = threadIdx.y; i < 32; i += 8)
        t[i][threadIdx.x] = in[(size_t)(k0 + i) * N + n0 + threadIdx.x];
    __syncthreads();
    for (int i = threadIdx.y; i < 32; i += 8)
        out[(size_t)(n0 + i) * K + k0 + threadIdx.x] = __float2half(t[threadIdx.x][i]);
}

// Folded layer weights: out[n*K+k] = h( beta*W[k][n] + (k==n)*(1-beta) ), layer = blockIdx.z
__global__ void k_transpose_fold(const float* __restrict__ in, __half* __restrict__ out,
                                 int K, int N) {
    __shared__ float t[32][33];
    int l = blockIdx.z;
    float beta = logf(0.5f / (float)(l + 1) + 1.0f);
    int k0 = blockIdx.x * 32, n0 = blockIdx.y * 32;
    const float* src = in  + (size_t)l * K * N;
    __half*      dst = out + (size_t)l * K * N;
    for (int i = threadIdx.y; i < 32; i += 8)
        t[i][threadIdx.x] = src[(size_t)(k0 + i) * N + n0 + threadIdx.x];
    __syncthreads();
    for (int i = threadIdx.y; i < 32; i += 8) {
        int k = k0 + threadIdx.x, nn = n0 + i;
        float v = beta * t[threadIdx.x][i] + ((k == nn) ? (1.0f - beta) : 0.0f);
        dst[(size_t)nn * K + k] = __float2half(v);
    }
}

// ---------------- SpMM (all-fp16 I/O, fp32 accum): one warp per node ----------------
__global__ void __launch_bounds__(256) k_spmm16(const __half* __restrict__ hin,
                                                const __half* __restrict__ res,
                                                __half* __restrict__ outp,
                                                int n) {
    int warp = (blockIdx.x * blockDim.x + threadIdx.x) >> 5;
    int lane = threadIdx.x & 31;
    if (warp >= n) return;
    int node = warp;

    const uint4* hin4 = (const uint4*)hin;   // 8 halves per uint4; 32 uint4 per row

    float di = g_dinv[node];
    float ws = di * di;

    float acc[8];
    {
        uint4 v = hin4[(size_t)node * 32 + lane];
        const __half2* h2 = (const __half2*)&v;
        #pragma unroll
        for (int q = 0; q < 4; q++) {
            float2 f = __half22float2(h2[q]);
            acc[q * 2]     = ws * f.x;
            acc[q * 2 + 1] = ws * f.y;
        }
    }

    int start = g_rowptr[node];
    int end   = g_rowptr[node + 1];
    for (int p0 = start; p0 < end; p0 += 32) {
        int myp = p0 + lane;
        int src = 0;
        float w = 0.f;
        if (myp < end) {
            src = g_srcs[myp];
            w   = g_wts[myp];
        }
        int cnt = min(32, end - p0);
        #pragma unroll 4
        for (int j = 0; j < cnt; j++) {
            int   s  = __shfl_sync(0xffffffffu, src, j);
            float wj = __shfl_sync(0xffffffffu, w, j);
            uint4 v = hin4[(size_t)s * 32 + lane];
            const __half2* h2 = (const __half2*)&v;
            #pragma unroll
            for (int q = 0; q < 4; q++) {
                float2 f = __half22float2(h2[q]);
                acc[q * 2]     += wj * f.x;
                acc[q * 2 + 1] += wj * f.y;
            }
        }
    }

    uint4 rv = ((const uint4*)res)[(size_t)node * 32 + lane];
    const __half2* r2 = (const __half2*)&rv;
    uint4 ov;
    __half2* o2 = (__half2*)&ov;
    #pragma unroll
    for (int q = 0; q < 4; q++) {
        float2 f = __half22float2(r2[q]);
        o2[q] = __floats2half2_rn((1.f - ALPHA) * acc[q * 2]     + ALPHA * f.x,
                                  (1.f - ALPHA) * acc[q * 2 + 1] + ALPHA * f.y);
    }
    ((uint4*)outp)[(size_t)node * 32 + lane] = ov;
}

// ====== FP16 mma.sync GEMM: 128x128 tile, 128 thr / 4 warps (64x64 each), ======
// ====== BK=64, ldmatrix + 3-stage cp.async — R9 winner, half the barriers  ======
// A16 row-major [M,K] fp16, B16 K-major [N,K] fp16 (= col-major B), fp32 accum.
// smem rows = 64 halves (128B = 8 x 16B chunks); chunk swizzle c ^ (row&7)
// (SW128) — conflict-free for cp.async stores AND ldmatrix phases.
#define STAGE_B 32768                // bytes per stage: A 16KB + B 16KB
#define GEMM_SMEM (3 * STAGE_B)      // 96 KB dynamic

__global__ void __launch_bounds__(128, 2) k_hgemm(const __half* __restrict__ A16,
                                                  const __half* __restrict__ B16,
                                                  const float* __restrict__ bias,
                                                  float* __restrict__ out32,
                                                  __half* __restrict__ out16,
                                                  int M, int K, int do_relu) {
    extern __shared__ __align__(16) uint32_t smem[];

    const int tid  = threadIdx.x;
    const int warp = tid >> 5;
    const int lane = tid & 31;
    const int gid  = lane >> 2;   // 0..7
    const int tig  = lane & 3;    // 0..3
    const int wm   = warp >> 1;   // 0..1  (M offset wm*64)
    const int wn   = warp & 1;    // 0..1  (N offset wn*64)
    const int rowBase = blockIdx.y * 128;
    const int colBase = blockIdx.x * 128;

    const int nch = K >> 6;       // chunks of K=64

    float acc[4][8][4];
    #pragma unroll
    for (int i = 0; i < 4; i++)
        #pragma unroll
        for (int j = 0; j < 8; j++)
            #pragma unroll
            for (int q = 0; q < 4; q++) acc[i][j][q] = 0.f;

    const uint32_t smem_base = smem_u32(smem);

    // ---- precomputed ldmatrix lane offsets (stage-relative), ks = k16 block 0..3 ----
    uint32_t offA[4], offB[4];
    {
        int rA = (lane & 7) + ((lane >> 3) & 1) * 8;   // row within 16-row A frag
        int cA = (lane >> 4) & 1;                      // 16B chunk within k16 block
        int rowA = wm * 64 + rA;
        int sA = rowA & 7;
        int rB = (lane & 7) + ((lane >> 4) & 1) * 8;   // row within B pair frag
        int cB = (lane >> 3) & 1;
        int rowB = wn * 64 + rB;
        int sB = rowB & 7;
        #pragma unroll
        for (int ks = 0; ks < 4; ks++) {
            offA[ks] = (uint32_t)(rowA * 128 + (((ks * 2 + cA) ^ sA) << 4));
            offB[ks] = (uint32_t)(16384 + rowB * 128 + (((ks * 2 + cB) ^ sB) << 4));
        }
    }

    auto load_chunk = [&](int c) {
        const int k0 = c << 6;
        const uint32_t stg = smem_base + (uint32_t)((c % 3) * STAGE_B);
        #pragma unroll
        for (int p = 0; p < 8; p++) {   // A: 128 rows x 8 chunks, 128 thr -> 8 each
            int r  = p * 16 + (tid >> 3);
            int c8 = tid & 7;
            int gr = min(rowBase + r, M - 1);
            cp_async16(stg + (uint32_t)(r * 128 + ((c8 ^ (r & 7)) << 4)),
                       &A16[(size_t)gr * K + k0 + c8 * 8]);
        }
        const uint32_t stgB = stg + 16384;
        #pragma unroll
        for (int p = 0; p < 8; p++) {   // B: 128 rows x 8 chunks
            int r  = p * 16 + (tid >> 3);
            int c8 = tid & 7;
            cp_async16(stgB + (uint32_t)(r * 128 + ((c8 ^ (r & 7)) << 4)),
                       &B16[(size_t)(colBase + r) * K + k0 + c8 * 8]);
        }
        CP_COMMIT();
    };

    load_chunk(0);
    if (nch > 1) load_chunk(1);

    for (int c = 0; c < nch; c++) {
        if (c + 1 < nch) { CP_WAIT(1); } else { CP_WAIT(0); }
        __syncthreads();                    // stage c ready; all warps past compute c-1
        if (c + 2 < nch) load_chunk(c + 2); // overwrites stage (c-1)%3 — safe after sync

        const uint32_t stg = smem_base + (uint32_t)((c % 3) * STAGE_B);

        #pragma unroll
        for (int ks = 0; ks < 4; ks++) {
            uint32_t af[4][4];
            #pragma unroll
            for (int mt = 0; mt < 4; mt++)
                ldsm_x4(af[mt][0], af[mt][1], af[mt][2], af[mt][3],
                        stg + offA[ks] + (uint32_t)(mt * 2048));
            uint32_t bf[8][2];
            #pragma unroll
            for (int p = 0; p < 4; p++)
                ldsm_x4(bf[2 * p][0], bf[2 * p][1], bf[2 * p + 1][0], bf[2 * p + 1][1],
                        stg + offB[ks] + (uint32_t)(p * 2048));
            #pragma unroll
            for (int mt = 0; mt < 4; mt++)
                #pragma unroll
                for (int nt = 0; nt < 8; nt++) {
                    asm volatile(
                        "mma.sync.aligned.m16n8k16.row.col.f32.f16.f16.f32 "
                        "{%0,%1,%2,%3}, {%4,%5,%6,%7}, {%8,%9}, {%0,%1,%2,%3};"
                        : "+f"(acc[mt][nt][0]), "+f"(acc[mt][nt][1]),
                          "+f"(acc[mt][nt][2]), "+f"(acc[mt][nt][3])
                        : "r"(af[mt][0]), "r"(af[mt][1]), "r"(af[mt][2]), "r"(af[mt][3]),
                          "r"(bf[nt][0]), "r"(bf[nt][1]));
                }
        }
    }

    // ---- epilogue ----
    #pragma unroll
    for (int mt = 0; mt < 4; mt++) {
        int rbase = rowBase + wm * 64 + mt * 16 + gid;
        #pragma unroll
        for (int nt = 0; nt < 8; nt++) {
            int cc = colBase + wn * 64 + nt * 8 + tig * 2;
            #pragma unroll
            for (int half = 0; half < 2; half++) {
                int r = rbase + half * 8;
                if (r >= M) continue;
                float v0 = acc[mt][nt][half * 2 + 0];
                float v1 = acc[mt][nt][half * 2 + 1];
                if (bias) {
                    v0 += bias[cc];
                    v1 += bias[cc + 1];
                }
                if (do_relu) {
                    v0 = fmaxf(v0, 0.f);
                    v1 = fmaxf(v1, 0.f);
                }
                size_t o = (size_t)r * HID + cc;
                if (out32) {
                    float2 vo; vo.x = v0; vo.y = v1;
                    *(float2*)&out32[o] = vo;
                }
                if (out16)
                    *(__half2*)&out16[o] = __floats2half2_rn(v0, v1);
            }
        }
    }
}

// ---------------- host orchestration ----------------
extern "C" void kernel_launch(void* const* d_in, const int* in_sizes, int n_in,
                              void* d_out, int out_size) {
    const float* x      = (const float*)d_in[0];
    const int*   ei     = (const int*)d_in[1];
    const float* Wemb   = (const float*)d_in[2];
    const float* bemb   = (const float*)d_in[3];
    const float* Wconvs = (const float*)d_in[4];
    float* out = (float*)d_out;

    int M = in_sizes[0] / INC;
    int E = in_sizes[1] / 2;

    __half *x16, *h016, *h16, *p16, *W16E, *W16L;
    cudaGetSymbolAddress((void**)&x16,  g_x16);
    cudaGetSymbolAddress((void**)&h016, g_h016);
    cudaGetSymbolAddress((void**)&h16,  g_h16);
    cudaGetSymbolAddress((void**)&p16,  g_p16);
    cudaGetSymbolAddress((void**)&W16E, g_W16E);
    cudaGetSymbolAddress((void**)&W16L, g_W16L);

    cudaFuncSetAttribute(k_hgemm, cudaFuncAttributeMaxDynamicSharedMemorySize, GEMM_SMEM);

    const int T = 256;
    int nbN = (M + T - 1) / T;
    int nbE = (E + T - 1) / T;
    int nbScan = (M + 1023) / 1024;
    dim3 ggrid(HID / 128, (M + 127) / 128);

    // weights + x conversion first; embed GEMM is the 4th launch (ncu window)
    k_transpose_h<<<dim3(INC / 32, HID / 32), dim3(32, 8)>>>(Wemb, W16E, INC, HID);
    k_transpose_fold<<<dim3(HID / 32, HID / 32, NLAYER), dim3(32, 8)>>>(Wconvs, W16L, HID, HID);
    {
        size_t n8 = (size_t)M * INC / 8;
        k_tohalf<<<(unsigned)((n8 + 255) / 256), 256>>>(x, x16, n8);
    }

    // embed: h016 = h16(relu(x @ Wemb + bemb))
    k_hgemm<<<ggrid, 128, GEMM_SMEM>>>(x16, W16E, bemb, nullptr, h016, M, INC, 1);

    // graph preprocessing
    k_deg_init<<<nbN, T>>>(M);
    k_deg_count<<<nbE, T>>>(ei, E);
    k_dinv<<<nbN, T>>>(M);
    k_scan_blocks<<<nbScan, 1024>>>(M);
    k_scan_sums<<<1, 128>>>(nbScan);
    k_finalize_ptrs<<<nbN, T>>>(M);
    k_scatter<<<nbE, T>>>(ei, E);

    // layers: SpMM (fp16 in/out) then folded-weight GEMM
    int spmmBlocks = ((M * 32) + T - 1) / T;
    for (int l = 0; l < NLAYER; l++) {
        const __half* gatherIn = (l == 0) ? h016 : h16;
        k_spmm16<<<spmmBlocks, T>>>(gatherIn, h016, p16, M);
        int last = (l == NLAYER - 1);
        if (last)
            k_hgemm<<<ggrid, 128, GEMM_SMEM>>>(p16, W16L + (size_t)l * HID * HID, nullptr,
                                               out, nullptr, M, HID, 0);
        else
            k_hgemm<<<ggrid, 128, GEMM_SMEM>>>(p16, W16L + (size_t)l * HID * HID, nullptr,
                                               nullptr, h16, M, HID, 1);
    }
}